// round 17
// baseline (speedup 1.0000x reference)
#include <cuda_runtime.h>
#include <math.h>

#define NB   32
#define NS   4096
#define ND   64
#define NL   13
#define NWR  13
#define NCLS 2
#define ROWS (NB*NS)          // 131072
#define SD   (NS*ND)          // 262144
#define VOCAB 512
#define NP   7                // F pairs per row (13 -> 7 float2)

__device__ float  g_Vtab[VOCAB*ND];                 // [v][64]
__device__ float  g_Ftab[(size_t)NWR*VOCAB*16];     // [k][v][16] (13 used)
__device__ float2 g_FgT2[(size_t)NWR*NB*NP*NS];     // [kb][p][i]  95.4 MB
__device__ float  g_Zdump[(size_t)ROWS*ND];         // fallback Z sink

__device__ __forceinline__ float gelu_exact(float x) {
    return 0.5f * x * (1.0f + erff(x * 0.7071067811865476f));
}

// ---------------------------------------------------------------------------
// Tables: grid (32, 14), block 256. y==0 -> Vtab else Ftab[y-1].
// V path reads vW2 directly from gmem (no W2s staging) -> 52KB smem.
// ---------------------------------------------------------------------------
__global__ __launch_bounds__(256) void tables_kernel(
    const float* __restrict__ emb,
    const float* __restrict__ fW1, const float* __restrict__ fb1,
    const float* __restrict__ fW2, const float* __restrict__ fb2,
    const float* __restrict__ vW1, const float* __restrict__ vb1,
    const float* __restrict__ vW2, const float* __restrict__ vb2) {
    extern __shared__ float sm[];
    float* Es  = sm;                    // 1024
    float* W1s = sm + 1024;             // 8192
    float* Hs  = sm + 9216;             // 2176
    float* W2s = sm + 11392;            // 1664 (F path only)

    const int y  = blockIdx.y;
    const int v0 = blockIdx.x * 16;
    const int t  = threadIdx.x;

    {
        float4*       Es4 = (float4*)Es;
        const float4* eg  = (const float4*)(emb + v0*64);
        Es4[t] = eg[t];
        float4*       W14 = (float4*)W1s;
        const float4* w1g = (const float4*)((y == 0) ? vW1 : fW1 + (size_t)(y-1)*64*128);
#pragma unroll
        for (int i = 0; i < 8; i++) W14[t + 256*i] = w1g[t + 256*i];
        if (y != 0) {
            const float* W2g = fW2 + (size_t)(y-1)*128*NL;
            for (int i = t; i < 128*NL; i += 256) W2s[i] = W2g[i];
        }
    }
    __syncthreads();

    {
        const int h  = t & 127;
        const int rg = t >> 7;
        const float b1 = (y == 0) ? vb1[h] : fb1[(y-1)*128 + h];
        float acc[8];
#pragma unroll
        for (int rr = 0; rr < 8; rr++) acc[rr] = 0.f;
#pragma unroll
        for (int dc = 0; dc < 4; dc++) {
            float w[16];
#pragma unroll
            for (int j = 0; j < 16; j++) w[j] = W1s[(dc*16 + j)*128 + h];
#pragma unroll
            for (int rr = 0; rr < 8; rr++) {
                const int r = rg*8 + rr;
                const float4* e4 = (const float4*)(Es + r*64 + dc*16);
#pragma unroll
                for (int j4 = 0; j4 < 4; j4++) {
                    float4 e = e4[j4];
                    acc[rr] = fmaf(e.x, w[4*j4+0], acc[rr]);
                    acc[rr] = fmaf(e.y, w[4*j4+1], acc[rr]);
                    acc[rr] = fmaf(e.z, w[4*j4+2], acc[rr]);
                    acc[rr] = fmaf(e.w, w[4*j4+3], acc[rr]);
                }
            }
        }
#pragma unroll
        for (int rr = 0; rr < 8; rr++)
            Hs[h*17 + rg*8 + rr] = gelu_exact(acc[rr] + b1);
    }
    __syncthreads();

    if (y == 0) {
        const int d = t & 63, rgrp = t >> 6;
        float a[4];
#pragma unroll
        for (int rr = 0; rr < 4; rr++) a[rr] = vb2[d];
#pragma unroll 4
        for (int h2 = 0; h2 < 128; h2++) {
            const float wv = __ldg(vW2 + h2*64 + d);   // L1-resident
#pragma unroll
            for (int rr = 0; rr < 4; rr++)
                a[rr] = fmaf(Hs[h2*17 + rgrp*4 + rr], wv, a[rr]);
        }
#pragma unroll
        for (int rr = 0; rr < 4; rr++)
            g_Vtab[(size_t)(v0 + rgrp*4 + rr)*64 + d] = a[rr];
    } else {
        const int k = y - 1;
        if (t < 16*NL) {
            const int l = t >> 4, r = t & 15;
            float a0=0.f, a1=0.f, a2=0.f, a3=0.f;
#pragma unroll
            for (int h4 = 0; h4 < 32; h4++) {
                a0 = fmaf(Hs[(4*h4+0)*17 + r], W2s[(4*h4+0)*NL + l], a0);
                a1 = fmaf(Hs[(4*h4+1)*17 + r], W2s[(4*h4+1)*NL + l], a1);
                a2 = fmaf(Hs[(4*h4+2)*17 + r], W2s[(4*h4+2)*NL + l], a2);
                a3 = fmaf(Hs[(4*h4+3)*17 + r], W2s[(4*h4+3)*NL + l], a3);
            }
            g_Ftab[((size_t)k*VOCAB + v0 + r)*16 + l] = fb2[k*NL + l] + ((a0+a1)+(a2+a3));
        }
    }
}

// ---------------------------------------------------------------------------
// Fused fgather + logits. Blocks [0, 3328): fgather (2 rows/thread, float2
// pair planes); blocks [3328, 3840): logits.
// ---------------------------------------------------------------------------
__global__ __launch_bounds__(256) void fgather_logits_kernel(
    const int* __restrict__ tok,
    const float* __restrict__ finW, const float* __restrict__ finb,
    float* __restrict__ out) {
    const int bx = blockIdx.x;
    const int t  = threadIdx.x;
    __shared__ float red[256];

    if (bx < 3328) {
        const int kb = bx >> 3;          // k*NB + b
        const int k  = kb >> 5;
        const int b  = kb & 31;
        const int i0 = (bx & 7) * 512 + t;

        const float4* Ft4 = (const float4*)g_Ftab + (size_t)k*VOCAB*4;
        float2* dst = g_FgT2 + (size_t)kb*NP*NS;
        const int* tkb = tok + (size_t)b*NS;

        const int ia = i0, ib = i0 + 256;
        const int va = tkb[ia], vb = tkb[ib];
        float4 a0 = Ft4[va*4], a1 = Ft4[va*4+1], a2 = Ft4[va*4+2], a3 = Ft4[va*4+3];
        float4 b0 = Ft4[vb*4], b1 = Ft4[vb*4+1], b2 = Ft4[vb*4+2], b3 = Ft4[vb*4+3];
        const float2 pa[NP] = {{a0.x,a0.y},{a0.z,a0.w},{a1.x,a1.y},{a1.z,a1.w},
                               {a2.x,a2.y},{a2.z,a2.w},{a3.x,0.f}};
        const float2 pb[NP] = {{b0.x,b0.y},{b0.z,b0.w},{b1.x,b1.y},{b1.z,b1.w},
                               {b2.x,b2.y},{b2.z,b2.w},{b3.x,0.f}};
#pragma unroll
        for (int p = 0; p < NP; p++) {
            dst[(size_t)p*NS + ia] = pa[p];
            dst[(size_t)p*NS + ib] = pb[p];
        }
    } else {
        const int lx = bx - 3328;
        const int s = lx & 7;
        const int c = (lx >> 3) & 1;
        const int b = lx >> 4;
        const int chunk = SD/4/8;   // 8192 float4

        const float4* Vt4 = (const float4*)g_Vtab;
        const float4* w   = (const float4*)(finW + (size_t)c*SD) + s*chunk;
        const int*    tkb = tok + (size_t)b*NS;

        float acc = 0.f;
        for (int i = t; i < chunk; i += 256) {
            int gi   = s*chunk + i;
            int srow = gi >> 4;
            int d4   = gi & 15;
            float4 vv = Vt4[tkb[srow]*16 + d4];
            float4 ww = w[i];
            acc = fmaf(vv.x, ww.x, acc);
            acc = fmaf(vv.y, ww.y, acc);
            acc = fmaf(vv.z, ww.z, acc);
            acc = fmaf(vv.w, ww.w, acc);
        }
        red[t] = acc;
        __syncthreads();
#pragma unroll
        for (int sft = 128; sft > 0; sft >>= 1) {
            if (t < sft) red[t] += red[t + sft];
            __syncthreads();
        }
        if (t == 0) atomicAdd(&out[b*NCLS + c], red[0] + (s == 0 ? finb[c] : 0.f));
    }
}

// ---------------------------------------------------------------------------
// Fused chord: ping-pong Z planes, vreg residual, one sync/round.
// F read as 7 LDG.64 per (t,m) from the float2 pair planes (halved LDG issue).
// ---------------------------------------------------------------------------
__global__ __launch_bounds__(1024, 1) void chord_all_kernel(
    const int* __restrict__ tok, float* __restrict__ outZ) {
    extern __shared__ float sm[];
    float4* Z0 = (float4*)sm;            // [i], 64 KB
    float4* Z1 = Z0 + NS;                // [i], 64 KB

    const int b  = blockIdx.x >> 4;
    const int cp = blockIdx.x & 15;
    const int c0 = cp * 4;
    const int t  = threadIdx.x;

    float4 zreg[4], vreg[4];
    {
        const int* tkb = tok + (size_t)b*NS;
#pragma unroll
        for (int m = 0; m < 4; m++) {
            const int i = t + 1024*m;
            const int v = tkb[i];
            float4 a = *(const float4*)(g_Vtab + (size_t)v*64 + c0);
            vreg[m] = a;
            zreg[m] = a;
            Z0[i] = a;
        }
    }
    __syncthreads();

#pragma unroll 1
    for (int k = 0; k < NWR; k++) {
        const float4* Zr = (k & 1) ? Z1 : Z0;
        float4*       Zw = (k & 1) ? Z0 : Z1;
        const float2* Fb = g_FgT2 + ((size_t)(k*NB + b)*NP)*NS + t;
        const float4 st0 = zreg[0], st1 = zreg[1];
#pragma unroll
        for (int m = 0; m < 4; m++) {
            const int i = t + 1024*m;
            const float2* fp = Fb + 1024*m;
            const float2 p0 = fp[0];
            const float2 p1 = fp[(size_t)1*NS], p2 = fp[(size_t)2*NS];
            const float2 p3 = fp[(size_t)3*NS], p4 = fp[(size_t)4*NS];
            const float2 p5 = fp[(size_t)5*NS], p6 = fp[(size_t)6*NS];
            const float f0  = p0.x, f1  = p0.y, f2  = p1.x, f3  = p1.y;
            const float f4  = p2.x, f5  = p2.y, f6  = p3.x, f7  = p3.y;
            const float f8  = p4.x, f9  = p4.y, f10 = p5.x, f11 = p5.y;
            const float f12 = p6.x;

            float4 a = vreg[m];

            const float4 zm  = zreg[m];
            const float4 zm1 = (m == 3) ? st0 : zreg[(m+1)&3];
            const float4 zm2 = (m == 2) ? st0 : ((m == 3) ? st1 : zreg[(m+2)&3]);
            a.x = fmaf(f0,  zm.x,  a.x); a.y = fmaf(f0,  zm.y,  a.y);
            a.z = fmaf(f0,  zm.z,  a.z); a.w = fmaf(f0,  zm.w,  a.w);
            a.x = fmaf(f11, zm1.x, a.x); a.y = fmaf(f11, zm1.y, a.y);
            a.z = fmaf(f11, zm1.z, a.z); a.w = fmaf(f11, zm1.w, a.w);
            a.x = fmaf(f12, zm2.x, a.x); a.y = fmaf(f12, zm2.y, a.y);
            a.z = fmaf(f12, zm2.z, a.z); a.w = fmaf(f12, zm2.w, a.w);

            const float fs[10] = {f1,f2,f3,f4,f5,f6,f7,f8,f9,f10};
            const int offs[10] = {1,2,4,8,16,32,64,128,256,512};
#pragma unroll
            for (int li = 0; li < 10; li++) {
                const int j = (i + offs[li]) & (NS-1);
                const float fl = fs[li];
                float4 z = Zr[j];
                a.x = fmaf(fl, z.x, a.x); a.y = fmaf(fl, z.y, a.y);
                a.z = fmaf(fl, z.z, a.z); a.w = fmaf(fl, z.w, a.w);
            }

            Zw[i] = a;
            zreg[m] = a;
        }
        __syncthreads();
    }

#pragma unroll
    for (int m = 0; m < 4; m++) {
        const int i = t + 1024*m;
        *(float4*)(outZ + ((size_t)b*NS + i)*64 + c0) = zreg[m];
    }
}

// ---------------------------------------------------------------------------
extern "C" void kernel_launch(void* const* d_in, const int* in_sizes, int n_in,
                              void* d_out, int out_size) {
    const int*   tok  = (const int*)  d_in[0];
    const float* emb  = (const float*)d_in[1];
    const float* fW1  = (const float*)d_in[2];
    const float* fb1  = (const float*)d_in[3];
    const float* fW2  = (const float*)d_in[4];
    const float* fb2  = (const float*)d_in[5];
    const float* vW1  = (const float*)d_in[6];
    const float* vb1  = (const float*)d_in[7];
    const float* vW2  = (const float*)d_in[8];
    const float* vb2  = (const float*)d_in[9];
    const float* finW = (const float*)d_in[10];
    const float* finb = (const float*)d_in[11];
    float* out = (float*)d_out;

    const int tables_smem = (1024 + 8192 + 2176 + 1664) * 4;   // 52224 -> 4 CTAs/SM
    const int chord_smem  = NS * 2 * 16;                       // 131072
    cudaFuncSetAttribute(tables_kernel,    cudaFuncAttributeMaxDynamicSharedMemorySize, tables_smem);
    cudaFuncSetAttribute(chord_all_kernel, cudaFuncAttributeMaxDynamicSharedMemorySize, chord_smem);

    cudaMemsetAsync(out, 0, NB*NCLS*sizeof(float));

    dim3 tgrid(32, 14);
    tables_kernel<<<tgrid, 256, tables_smem>>>(emb, fW1, fb1, fW2, fb2,
                                               vW1, vb1, vW2, vb2);

    fgather_logits_kernel<<<3328 + 512, 256>>>(tok, finW, finb, out);

    float* zdst;
    if (out_size >= NB*NCLS + ROWS*ND) zdst = out + NB*NCLS;
    else cudaGetSymbolAddress((void**)&zdst, g_Zdump);
    chord_all_kernel<<<NB*16, 1024, chord_smem>>>(tok, zdst);
}